// round 3
// baseline (speedup 1.0000x reference)
#include <cuda_runtime.h>

// R3: two-kernel scheme. Everything before attention depends only on
// (digit, t) -> only 10*64 = 640 distinct (Q,K,V) triples. Kernel 1
// precomputes them (plus digit table + positional-encoding vector) into
// __device__ tables; the main kernel's prologue collapses to table loads.
// Attention loop unchanged from R2: packed fma.rn.f32x2, 2 s-positions/iter,
// max-free softmax with 0.5*log2e folded into q.

#define T 64
#define BPB 4
#define NTHREADS (BPB * T)
#define VOCAB 10

typedef unsigned long long u64;

__device__ float4 g_qtab[VOCAB * T];
__device__ float4 g_ktab[VOCAB * T];
__device__ float4 g_vtab[VOCAB * T];
__device__ float2 g_tok[VOCAB];
__device__ float  g_pe[T];

__device__ __forceinline__ float ex2f(float x) {
    float y; asm("ex2.approx.ftz.f32 %0, %1;" : "=f"(y) : "f"(x)); return y;
}
__device__ __forceinline__ float rcpf(float x) {
    float y; asm("rcp.approx.ftz.f32 %0, %1;" : "=f"(y) : "f"(x)); return y;
}
__device__ __forceinline__ u64 pack2(float lo, float hi) {
    u64 r; asm("mov.b64 %0, {%1, %2};" : "=l"(r) : "f"(lo), "f"(hi)); return r;
}
__device__ __forceinline__ void unpack2(u64 v, float& lo, float& hi) {
    asm("mov.b64 {%0, %1}, %2;" : "=f"(lo), "=f"(hi) : "l"(v));
}
__device__ __forceinline__ u64 fma2(u64 a, u64 b, u64 c) {
    u64 d; asm("fma.rn.f32x2 %0, %1, %2, %3;" : "=l"(d) : "l"(a), "l"(b), "l"(c)); return d;
}
__device__ __forceinline__ u64 mul2(u64 a, u64 b) {
    u64 d; asm("mul.rn.f32x2 %0, %1, %2;" : "=l"(d) : "l"(a), "l"(b)); return d;
}
__device__ __forceinline__ u64 add2(u64 a, u64 b) {
    u64 d; asm("add.rn.f32x2 %0, %1, %2;" : "=l"(d) : "l"(a), "l"(b)); return d;
}

// ---------------- kernel 1: 640-entry (Q,K,V) table ----------------
__global__ void precompute_kernel(
    const float* __restrict__ pA,
    const float* __restrict__ pStart,
    const float* __restrict__ pStride,
    const float* __restrict__ w_ln1,
    const float* __restrict__ w_qn,
    const float* __restrict__ Wq,
    const float* __restrict__ Wk)
{
    const int dig = blockIdx.x;    // 0..9
    const int t   = threadIdx.x;   // 0..63

    const float A = pA[0], astart = pStart[0], astride = pStride[0];
    float sa, ca;
    sincosf(astart + (float)dig * astride, &sa, &ca);
    const float x0 = A * ca;
    const float x1 = A * sa;
    const float x2 = sinf((float)t * 1.0e-4f);

    if (t == 0)  g_tok[dig] = make_float2(x0, x1);
    if (dig == 0) g_pe[t] = x2;

    // RMS ln1
    const float r = rsqrtf((x0*x0 + x1*x1 + x2*x2) * (1.0f/3.0f) + 1e-6f);
    const float h0 = x0 * r * w_ln1[0];
    const float h1 = x1 * r * w_ln1[1];
    const float h2 = x2 * r * w_ln1[2];

    float qr[4], kv[4];
#pragma unroll
    for (int j = 0; j < 4; ++j) {
        qr[j] = h0 * Wq[j*3+0] + h1 * Wq[j*3+1] + h2 * Wq[j*3+2];
        kv[j] = h0 * Wk[j*3+0] + h1 * Wk[j*3+1] + h2 * Wk[j*3+2];
    }

    const float rq = rsqrtf((qr[0]*qr[0]+qr[1]*qr[1]+qr[2]*qr[2]+qr[3]*qr[3]) * 0.25f + 1e-6f);
    const float rk = rsqrtf((kv[0]*kv[0]+kv[1]*kv[1]+kv[2]*kv[2]+kv[3]*kv[3]) * 0.25f + 1e-6f);
    float q0 = qr[0]*rq*w_qn[0], q1 = qr[1]*rq*w_qn[1];
    float q2 = qr[2]*rq*w_qn[2], q3 = qr[3]*rq*w_qn[3];
    float k0 = kv[0]*rk*w_qn[0], k1 = kv[1]*rk*w_qn[1];
    float k2 = kv[2]*rk*w_qn[2], k3 = kv[3]*rk*w_qn[3];

    // RoPE (theta=3, HD=4 -> inv_freq {1, 3^-0.5})
    float s0, c0, s1, c1;
    sincosf((float)t, &s0, &c0);
    sincosf((float)t * 0.57735026918962576f, &s1, &c1);

    float Q0 = q0*c0 - q1*s0, Q1 = q0*s0 + q1*c0;
    float Q2 = q2*c1 - q3*s1, Q3 = q2*s1 + q3*c1;
    float K0 = k0*c0 - k1*s0, K1 = k0*s0 + k1*c0;
    float K2 = k2*c1 - k3*s1, K3 = k2*s1 + k3*c1;

    const float SC = 0.5f * 1.4426950408889634f;   // scale * log2(e)
    const int e = dig * T + t;
    g_qtab[e] = make_float4(Q0*SC, Q1*SC, Q2*SC, Q3*SC);
    g_ktab[e] = make_float4(K0, K1, K2, K3);
    g_vtab[e] = make_float4(kv[0], kv[1], kv[2], kv[3]);
}

// ---------------- kernel 2: attention + FFN + logits ----------------
__global__ __launch_bounds__(NTHREADS)
void adder_model_kernel(
    const int* __restrict__ idx,
    const float* __restrict__ w_ln2,
    const float* __restrict__ w_lnf,
    const float* __restrict__ Wq,
    const float* __restrict__ Wg,
    const float* __restrict__ Wu,
    const float* __restrict__ Wd,
    float* __restrict__ out)
{
    __shared__ ulonglong2 kA[BPB][T/2];
    __shared__ ulonglong2 kB[BPB][T/2];
    __shared__ ulonglong2 vA[BPB][T/2];
    __shared__ ulonglong2 vB[BPB][T/2];
    __shared__ float2 tok_sh[VOCAB];
    __shared__ float  pe_sh[T];
    __shared__ float  logits_sh[BPB * T * VOCAB];

    const int tid   = threadIdx.x;
    const int local = tid >> 6;
    const int t     = tid & 63;
    const int b     = blockIdx.x * BPB + local;

    if (tid < VOCAB) tok_sh[tid] = g_tok[tid];
    if (tid < T)     pe_sh[tid]  = g_pe[tid];

    const int dig = idx[b * T + t];
    const int e   = dig * T + t;
    const float4 Q = g_qtab[e];
    const float4 K = g_ktab[e];
    const float4 V = g_vtab[e];

    // stage k/v pair-interleaved
    {
        const int i = t >> 1, lane = t & 1;
        float* a = (float*)&kA[local][i]; a[lane] = K.x; a[2+lane] = K.y;
        float* bb = (float*)&kB[local][i]; bb[lane] = K.z; bb[2+lane] = K.w;
        float* c = (float*)&vA[local][i]; c[lane] = V.x; c[2+lane] = V.y;
        float* d = (float*)&vB[local][i]; d[lane] = V.z; d[2+lane] = V.w;
    }
    __syncthreads();

    // residual input x (embedding)
    const float2 tk = tok_sh[dig];
    float x0 = tk.x, x1 = tk.y, x2 = pe_sh[t];

    // ---- causal attention, packed 2-wide, max-free ----
    const u64 Q0d = pack2(Q.x, Q.x), Q1d = pack2(Q.y, Q.y);
    const u64 Q2d = pack2(Q.z, Q.z), Q3d = pack2(Q.w, Q.w);

    u64 sum2 = 0ULL, c0a = 0ULL, c1a = 0ULL, c2a = 0ULL, c3a = 0ULL;
    const int np = (t + 1) >> 1;
#pragma unroll 4
    for (int i = 0; i < np; ++i) {
        const ulonglong2 ka = kA[local][i];
        const ulonglong2 kb = kB[local][i];
        const u64 sc2 = fma2(Q0d, ka.x, fma2(Q1d, ka.y, fma2(Q2d, kb.x, mul2(Q3d, kb.y))));
        float sl, sh; unpack2(sc2, sl, sh);
        const u64 p2 = pack2(ex2f(sl), ex2f(sh));
        sum2 = add2(sum2, p2);
        const ulonglong2 va = vA[local][i];
        const ulonglong2 vb = vB[local][i];
        c0a = fma2(p2, va.x, c0a);
        c1a = fma2(p2, va.y, c1a);
        c2a = fma2(p2, vb.x, c2a);
        c3a = fma2(p2, vb.y, c3a);
    }
    float sl, sh, a0, a1, a2, a3, tl, th;
    unpack2(sum2, sl, sh); float sum = sl + sh;
    unpack2(c0a, tl, th); a0 = tl + th;
    unpack2(c1a, tl, th); a1 = tl + th;
    unpack2(c2a, tl, th); a2 = tl + th;
    unpack2(c3a, tl, th); a3 = tl + th;

    if (!(t & 1)) {                 // leftover s = t
        const float sc = Q.x*K.x + Q.y*K.y + Q.z*K.z + Q.w*K.w;
        const float p  = ex2f(sc);
        sum += p;
        a0 += p * V.x; a1 += p * V.y; a2 += p * V.z; a3 += p * V.w;
    }

    const float inv = rcpf(sum);
    const float o0 = a0 * inv, o1 = a1 * inv, o2 = a2 * inv, o3 = a3 * inv;

    // ---- residual: x += out @ Wq ----
    x0 += o0*Wq[0] + o1*Wq[3] + o2*Wq[6] + o3*Wq[9];
    x1 += o0*Wq[1] + o1*Wq[4] + o2*Wq[7] + o3*Wq[10];
    x2 += o0*Wq[2] + o1*Wq[5] + o2*Wq[8] + o3*Wq[11];

    // ---- RMS ln2 + SwiGLU FFN ----
    float r = rsqrtf((x0*x0 + x1*x1 + x2*x2) * (1.0f/3.0f) + 1e-6f);
    const float h0 = x0 * r * w_ln2[0];
    const float h1 = x1 * r * w_ln2[1];
    const float h2 = x2 * r * w_ln2[2];

    const float g0 = h0*Wg[0] + h1*Wg[1] + h2*Wg[2];
    const float g1 = h0*Wg[3] + h1*Wg[4] + h2*Wg[5];
    const float u0 = h0*Wu[0] + h1*Wu[1] + h2*Wu[2];
    const float u1 = h0*Wu[3] + h1*Wu[4] + h2*Wu[5];

    const float LOG2E = 1.4426950408889634f;
    const float m0 = g0 * u0 * rcpf(1.0f + ex2f(-g0 * LOG2E));
    const float m1 = g1 * u1 * rcpf(1.0f + ex2f(-g1 * LOG2E));

    x0 += m0*Wd[0] + m1*Wd[1];
    x1 += m0*Wd[2] + m1*Wd[3];
    x2 += m0*Wd[4] + m1*Wd[5];

    // ---- final RMS; only first two channels feed logits ----
    r = rsqrtf((x0*x0 + x1*x1 + x2*x2) * (1.0f/3.0f) + 1e-6f);
    const float f0 = x0 * r * w_lnf[0];
    const float f1 = x1 * r * w_lnf[1];

    float* lg = &logits_sh[(local * T + t) * VOCAB];
#pragma unroll
    for (int vv = 0; vv < VOCAB; ++vv) {
        const float2 tb = tok_sh[vv];
        lg[vv] = f0 * tb.x + f1 * tb.y;
    }
    __syncthreads();

    float2* dst2 = (float2*)(out + (size_t)blockIdx.x * (BPB * T * VOCAB));
    const float2* src2 = (const float2*)logits_sh;
#pragma unroll
    for (int i = tid; i < BPB * T * VOCAB / 2; i += NTHREADS)
        dst2[i] = src2[i];
}

extern "C" void kernel_launch(void* const* d_in, const int* in_sizes, int n_in,
                              void* d_out, int out_size)
{
    const int*   idx     = (const int*)  d_in[0];
    const float* arc_A   = (const float*)d_in[1];
    const float* arc_st  = (const float*)d_in[2];
    const float* arc_sd  = (const float*)d_in[3];
    const float* w_ln1   = (const float*)d_in[4];
    const float* w_ln2   = (const float*)d_in[5];
    const float* w_lnf   = (const float*)d_in[6];
    const float* w_qn    = (const float*)d_in[7];
    const float* Wq      = (const float*)d_in[8];
    const float* Wk      = (const float*)d_in[9];
    const float* Wg      = (const float*)d_in[10];
    const float* Wu      = (const float*)d_in[11];
    const float* Wd      = (const float*)d_in[12];
    float* out = (float*)d_out;

    precompute_kernel<<<VOCAB, T>>>(arc_A, arc_st, arc_sd, w_ln1, w_qn, Wq, Wk);

    const int B = in_sizes[0] / T;           // 16384
    const int grid = B / BPB;                // 4096 blocks
    adder_model_kernel<<<grid, NTHREADS>>>(idx, w_ln2, w_lnf,
                                           Wq, Wg, Wu, Wd, out);
}

// round 4
// speedup vs baseline: 1.0491x; 1.0491x over previous
#include <cuda_runtime.h>

// R4: warp-per-batch, token-paired attention with conflict-free smem-SoA
// table gathers. Lane l owns tokens (l, 63-l); one packed loop covers both,
// token-1 masked via a -200 additive bias in its score FMA chain. k/v pair
// loads shared by both tokens: 128 LDS wavefronts/batch (was 192) and the
// (dig,t) gathers are now 1-wavefront LDS.32 (was ~30-wavefront LDG.128).
// Table smem aliased with logits staging smem.

#define T 64
#define WPB 8                     // warps (=batches) per block
#define NTHREADS (WPB * 32)
#define VOCAB 10

typedef unsigned long long u64;

__device__ float  g_tab[12 * VOCAB * T];   // SoA: [comp][dig*64+t], comp: Q0..3,K0..3,V0..3
__device__ float2 g_tok[VOCAB];
__device__ float  g_pe[T];

__device__ __forceinline__ float ex2f(float x) {
    float y; asm("ex2.approx.ftz.f32 %0, %1;" : "=f"(y) : "f"(x)); return y;
}
__device__ __forceinline__ float rcpf(float x) {
    float y; asm("rcp.approx.ftz.f32 %0, %1;" : "=f"(y) : "f"(x)); return y;
}
__device__ __forceinline__ u64 pack2(float lo, float hi) {
    u64 r; asm("mov.b64 %0, {%1, %2};" : "=l"(r) : "f"(lo), "f"(hi)); return r;
}
__device__ __forceinline__ void unpack2(u64 v, float& lo, float& hi) {
    asm("mov.b64 {%0, %1}, %2;" : "=f"(lo), "=f"(hi) : "l"(v));
}
__device__ __forceinline__ u64 fma2(u64 a, u64 b, u64 c) {
    u64 d; asm("fma.rn.f32x2 %0, %1, %2, %3;" : "=l"(d) : "l"(a), "l"(b), "l"(c)); return d;
}
__device__ __forceinline__ u64 mul2(u64 a, u64 b) {
    u64 d; asm("mul.rn.f32x2 %0, %1, %2;" : "=l"(d) : "l"(a), "l"(b)); return d;
}
__device__ __forceinline__ u64 add2(u64 a, u64 b) {
    u64 d; asm("add.rn.f32x2 %0, %1, %2;" : "=l"(d) : "l"(a), "l"(b)); return d;
}

// ---------------- kernel 1: 640-entry (Q,K,V) SoA table ----------------
__global__ void precompute_kernel(
    const float* __restrict__ pA,
    const float* __restrict__ pStart,
    const float* __restrict__ pStride,
    const float* __restrict__ w_ln1,
    const float* __restrict__ w_qn,
    const float* __restrict__ Wq,
    const float* __restrict__ Wk)
{
    const int dig = blockIdx.x;    // 0..9
    const int t   = threadIdx.x;   // 0..63

    const float A = pA[0], astart = pStart[0], astride = pStride[0];
    float sa, ca;
    sincosf(astart + (float)dig * astride, &sa, &ca);
    const float x0 = A * ca;
    const float x1 = A * sa;
    const float x2 = sinf((float)t * 1.0e-4f);

    if (t == 0)   g_tok[dig] = make_float2(x0, x1);
    if (dig == 0) g_pe[t] = x2;

    const float r = rsqrtf((x0*x0 + x1*x1 + x2*x2) * (1.0f/3.0f) + 1e-6f);
    const float h0 = x0 * r * w_ln1[0];
    const float h1 = x1 * r * w_ln1[1];
    const float h2 = x2 * r * w_ln1[2];

    float qr[4], kv[4];
#pragma unroll
    for (int j = 0; j < 4; ++j) {
        qr[j] = h0 * Wq[j*3+0] + h1 * Wq[j*3+1] + h2 * Wq[j*3+2];
        kv[j] = h0 * Wk[j*3+0] + h1 * Wk[j*3+1] + h2 * Wk[j*3+2];
    }

    const float rq = rsqrtf((qr[0]*qr[0]+qr[1]*qr[1]+qr[2]*qr[2]+qr[3]*qr[3]) * 0.25f + 1e-6f);
    const float rk = rsqrtf((kv[0]*kv[0]+kv[1]*kv[1]+kv[2]*kv[2]+kv[3]*kv[3]) * 0.25f + 1e-6f);
    float q0 = qr[0]*rq*w_qn[0], q1 = qr[1]*rq*w_qn[1];
    float q2 = qr[2]*rq*w_qn[2], q3 = qr[3]*rq*w_qn[3];
    float k0 = kv[0]*rk*w_qn[0], k1 = kv[1]*rk*w_qn[1];
    float k2 = kv[2]*rk*w_qn[2], k3 = kv[3]*rk*w_qn[3];

    float s0, c0, s1, c1;
    sincosf((float)t, &s0, &c0);
    sincosf((float)t * 0.57735026918962576f, &s1, &c1);

    float Q0 = q0*c0 - q1*s0, Q1 = q0*s0 + q1*c0;
    float Q2 = q2*c1 - q3*s1, Q3 = q2*s1 + q3*c1;
    float K0 = k0*c0 - k1*s0, K1 = k0*s0 + k1*c0;
    float K2 = k2*c1 - k3*s1, K3 = k2*s1 + k3*c1;

    const float SC = 0.5f * 1.4426950408889634f;   // scale * log2(e)
    const int e = dig * T + t;
    const int N = VOCAB * T;
    g_tab[0*N + e] = Q0*SC; g_tab[1*N + e] = Q1*SC;
    g_tab[2*N + e] = Q2*SC; g_tab[3*N + e] = Q3*SC;
    g_tab[4*N + e] = K0;    g_tab[5*N + e] = K1;
    g_tab[6*N + e] = K2;    g_tab[7*N + e] = K3;
    g_tab[8*N + e] = kv[0]; g_tab[9*N + e] = kv[1];
    g_tab[10*N + e] = kv[2]; g_tab[11*N + e] = kv[3];
}

// ---------------- kernel 2: attention + FFN + logits ----------------
__global__ __launch_bounds__(NTHREADS)
void adder_model_kernel(
    const int* __restrict__ idx,
    const float* __restrict__ w_ln2,
    const float* __restrict__ w_lnf,
    const float* __restrict__ Wq,
    const float* __restrict__ Wg,
    const float* __restrict__ Wu,
    const float* __restrict__ Wd,
    float* __restrict__ out)
{
    __shared__ union {
        float table[12 * VOCAB * T];          // 30720 B (gather phase)
        float logits[WPB * T * VOCAB];        // 20480 B (epilogue phase)
    } sm;
    __shared__ ulonglong2 kA[WPB][T/2];       // pair-interleaved K0K1
    __shared__ ulonglong2 kB[WPB][T/2];       // K2K3
    __shared__ ulonglong2 vA[WPB][T/2];
    __shared__ ulonglong2 vB[WPB][T/2];
    __shared__ float2 tok_sh[VOCAB];

    const int tid  = threadIdx.x;
    const int warp = tid >> 5;
    const int lane = tid & 31;
    const int b    = blockIdx.x * WPB + warp;

    if (tid < VOCAB) tok_sh[tid] = g_tok[tid];

    // stage SoA table into smem (coalesced)
    {
        const float4* src = (const float4*)g_tab;
        float4* dst = (float4*)sm.table;
#pragma unroll
        for (int i = tid; i < 12 * VOCAB * T / 4; i += NTHREADS)
            dst[i] = src[i];
    }
    __syncthreads();

    const int t1 = lane;              // 0..31
    const int t2 = 63 - lane;         // 32..63
    const int dig1 = idx[b * T + t1];
    const int dig2 = idx[b * T + t2];
    const int e1 = dig1 * T + t1;
    const int e2 = dig2 * T + t2;
    const int N = VOCAB * T;

    // conflict-free gathers (bank = t mod 32, lanes have distinct t)
    const float Q1x = sm.table[0*N+e1], Q1y = sm.table[1*N+e1];
    const float Q1z = sm.table[2*N+e1], Q1w = sm.table[3*N+e1];
    const float K1x = sm.table[4*N+e1], K1y = sm.table[5*N+e1];
    const float K1z = sm.table[6*N+e1], K1w = sm.table[7*N+e1];
    const float V1x = sm.table[8*N+e1], V1y = sm.table[9*N+e1];
    const float V1z = sm.table[10*N+e1], V1w = sm.table[11*N+e1];
    const float Q2x = sm.table[0*N+e2], Q2y = sm.table[1*N+e2];
    const float Q2z = sm.table[2*N+e2], Q2w = sm.table[3*N+e2];
    const float K2x = sm.table[4*N+e2], K2y = sm.table[5*N+e2];
    const float K2z = sm.table[6*N+e2], K2w = sm.table[7*N+e2];
    const float V2x = sm.table[8*N+e2], V2y = sm.table[9*N+e2];
    const float V2z = sm.table[10*N+e2], V2w = sm.table[11*N+e2];

    // stage k/v pair-interleaved for this warp's batch
    {
        int i = t1 >> 1, l = t1 & 1;
        float* p;
        p = (float*)&kA[warp][i]; p[l] = K1x; p[2+l] = K1y;
        p = (float*)&kB[warp][i]; p[l] = K1z; p[2+l] = K1w;
        p = (float*)&vA[warp][i]; p[l] = V1x; p[2+l] = V1y;
        p = (float*)&vB[warp][i]; p[l] = V1z; p[2+l] = V1w;
        i = t2 >> 1; l = t2 & 1;
        p = (float*)&kA[warp][i]; p[l] = K2x; p[2+l] = K2y;
        p = (float*)&kB[warp][i]; p[l] = K2z; p[2+l] = K2w;
        p = (float*)&vA[warp][i]; p[l] = V2x; p[2+l] = V2y;
        p = (float*)&vB[warp][i]; p[l] = V2z; p[2+l] = V2w;
    }
    __syncwarp();

    // ---- paired causal attention, packed 2-wide, max-free ----
    const u64 Q1xd = pack2(Q1x, Q1x), Q1yd = pack2(Q1y, Q1y);
    const u64 Q1zd = pack2(Q1z, Q1z), Q1wd = pack2(Q1w, Q1w);
    const u64 Q2xd = pack2(Q2x, Q2x), Q2yd = pack2(Q2y, Q2y);
    const u64 Q2zd = pack2(Q2z, Q2z), Q2wd = pack2(Q2w, Q2w);

    const int np1 = (t1 + 1) >> 1;    // token-1 full pairs
    const int np2 = (t2 + 1) >> 1;    // token-2 full pairs (loop bound)

    u64 s1d = 0ULL, a1x = 0ULL, a1y = 0ULL, a1z = 0ULL, a1w = 0ULL;
    u64 s2d = 0ULL, a2x = 0ULL, a2y = 0ULL, a2z = 0ULL, a2w = 0ULL;

#pragma unroll 2
    for (int i = 0; i < np2; ++i) {
        const ulonglong2 ka = kA[warp][i];
        const ulonglong2 kb = kB[warp][i];
        const ulonglong2 va = vA[warp][i];
        const ulonglong2 vb = vB[warp][i];

        // token 2 (always active)
        const u64 sc2 = fma2(Q2xd, ka.x, fma2(Q2yd, ka.y, fma2(Q2zd, kb.x, mul2(Q2wd, kb.y))));
        // token 1 (masked once i >= np1: -200 bias -> p ~ 0)
        const float mf = (i < np1) ? 0.0f : -200.0f;
        const u64 m1 = pack2(mf, mf);
        const u64 sc1 = fma2(Q1xd, ka.x, fma2(Q1yd, ka.y, fma2(Q1zd, kb.x, fma2(Q1wd, kb.y, m1))));

        float l2, h2f; unpack2(sc2, l2, h2f);
        const u64 p2 = pack2(ex2f(l2), ex2f(h2f));
        float l1, h1f; unpack2(sc1, l1, h1f);
        const u64 p1 = pack2(ex2f(l1), ex2f(h1f));

        s2d = add2(s2d, p2);
        a2x = fma2(p2, va.x, a2x); a2y = fma2(p2, va.y, a2y);
        a2z = fma2(p2, vb.x, a2z); a2w = fma2(p2, vb.y, a2w);
        s1d = add2(s1d, p1);
        a1x = fma2(p1, va.x, a1x); a1y = fma2(p1, va.y, a1y);
        a1z = fma2(p1, vb.x, a1z); a1w = fma2(p1, vb.y, a1w);
    }

    float lo, hi;
    unpack2(s1d, lo, hi); float sum1 = lo + hi;
    unpack2(a1x, lo, hi); float o1x = lo + hi;
    unpack2(a1y, lo, hi); float o1y = lo + hi;
    unpack2(a1z, lo, hi); float o1z = lo + hi;
    unpack2(a1w, lo, hi); float o1w = lo + hi;
    unpack2(s2d, lo, hi); float sum2 = lo + hi;
    unpack2(a2x, lo, hi); float o2x = lo + hi;
    unpack2(a2y, lo, hi); float o2y = lo + hi;
    unpack2(a2z, lo, hi); float o2z = lo + hi;
    unpack2(a2w, lo, hi); float o2w = lo + hi;

    if (!(t1 & 1)) {   // even t1: self term s=t1 from registers
        const float sc = Q1x*K1x + Q1y*K1y + Q1z*K1z + Q1w*K1w;
        const float p  = ex2f(sc);
        sum1 += p; o1x += p*V1x; o1y += p*V1y; o1z += p*V1z; o1w += p*V1w;
    } else {           // odd t1 -> even t2: self term s=t2
        const float sc = Q2x*K2x + Q2y*K2y + Q2z*K2z + Q2w*K2w;
        const float p  = ex2f(sc);
        sum2 += p; o2x += p*V2x; o2y += p*V2y; o2z += p*V2z; o2w += p*V2w;
    }

    {
        const float inv = rcpf(sum1);
        o1x *= inv; o1y *= inv; o1z *= inv; o1w *= inv;
    }
    {
        const float inv = rcpf(sum2);
        o2x *= inv; o2y *= inv; o2z *= inv; o2w *= inv;
    }

    // epilogue needs the table region for logits -> sync before aliased writes
    __syncthreads();

    // ---- per-token epilogue (residual + FFN + final RMS + logits) ----
#pragma unroll
    for (int which = 0; which < 2; ++which) {
        const int t   = which ? t2 : t1;
        const int dig = which ? dig2 : dig1;
        const float ox = which ? o2x : o1x, oy = which ? o2y : o1y;
        const float oz = which ? o2z : o1z, ow = which ? o2w : o1w;

        const float2 tk = tok_sh[dig];
        float x0 = tk.x, x1 = tk.y, x2 = g_pe[t];

        x0 += ox*Wq[0] + oy*Wq[3] + oz*Wq[6] + ow*Wq[9];
        x1 += ox*Wq[1] + oy*Wq[4] + oz*Wq[7] + ow*Wq[10];
        x2 += ox*Wq[2] + oy*Wq[5] + oz*Wq[8] + ow*Wq[11];

        float r = rsqrtf((x0*x0 + x1*x1 + x2*x2) * (1.0f/3.0f) + 1e-6f);
        const float h0 = x0 * r * w_ln2[0];
        const float h1 = x1 * r * w_ln2[1];
        const float h2 = x2 * r * w_ln2[2];

        const float g0 = h0*Wg[0] + h1*Wg[1] + h2*Wg[2];
        const float g1 = h0*Wg[3] + h1*Wg[4] + h2*Wg[5];
        const float u0 = h0*Wu[0] + h1*Wu[1] + h2*Wu[2];
        const float u1 = h0*Wu[3] + h1*Wu[4] + h2*Wu[5];

        const float LOG2E = 1.4426950408889634f;
        const float m0 = g0 * u0 * rcpf(1.0f + ex2f(-g0 * LOG2E));
        const float m1 = g1 * u1 * rcpf(1.0f + ex2f(-g1 * LOG2E));

        x0 += m0*Wd[0] + m1*Wd[1];
        x1 += m0*Wd[2] + m1*Wd[3];
        x2 += m0*Wd[4] + m1*Wd[5];

        r = rsqrtf((x0*x0 + x1*x1 + x2*x2) * (1.0f/3.0f) + 1e-6f);
        const float f0 = x0 * r * w_lnf[0];
        const float f1 = x1 * r * w_lnf[1];

        float* lg = &sm.logits[(warp * T + t) * VOCAB];
#pragma unroll
        for (int vv = 0; vv < VOCAB; ++vv) {
            const float2 tb = tok_sh[vv];
            lg[vv] = f0 * tb.x + f1 * tb.y;
        }
    }
    __syncthreads();

    // coalesced store: block owns a contiguous 5120-float span
    float2* dst2 = (float2*)(out + (size_t)blockIdx.x * (WPB * T * VOCAB));
    const float2* src2 = (const float2*)sm.logits;
#pragma unroll
    for (int i = tid; i < WPB * T * VOCAB / 2; i += NTHREADS)
        dst2[i] = src2[i];
}

extern "C" void kernel_launch(void* const* d_in, const int* in_sizes, int n_in,
                              void* d_out, int out_size)
{
    const int*   idx     = (const int*)  d_in[0];
    const float* arc_A   = (const float*)d_in[1];
    const float* arc_st  = (const float*)d_in[2];
    const float* arc_sd  = (const float*)d_in[3];
    const float* w_ln1   = (const float*)d_in[4];
    const float* w_ln2   = (const float*)d_in[5];
    const float* w_lnf   = (const float*)d_in[6];
    const float* w_qn    = (const float*)d_in[7];
    const float* Wq      = (const float*)d_in[8];
    const float* Wk      = (const float*)d_in[9];
    const float* Wg      = (const float*)d_in[10];
    const float* Wu      = (const float*)d_in[11];
    const float* Wd      = (const float*)d_in[12];
    float* out = (float*)d_out;

    precompute_kernel<<<VOCAB, T>>>(arc_A, arc_st, arc_sd, w_ln1, w_qn, Wq, Wk);

    const int B = in_sizes[0] / T;           // 16384
    const int grid = B / WPB;                // 2048 blocks
    adder_model_kernel<<<grid, NTHREADS>>>(idx, w_ln2, w_lnf,
                                           Wq, Wg, Wu, Wd, out);
}